// round 14
// baseline (speedup 1.0000x reference)
#include <cuda_runtime.h>
#include <cuda_fp16.h>
#include <math.h>
#include <stdint.h>

#define L     4
#define H     512
#define BATCH 32
#define TT    1024
#define G4    2048
#define LH    2048
#define JTOT  8192
#define NCTA  128
#define NTHR  512

#define SWZ(o) ((unsigned)(o) ^ (((unsigned)(o) >> 3) & 0x70u))

// ---- PTX helpers (base-target features only) ----
__device__ __forceinline__ uint32_t smem_u32(const void* p) {
    uint32_t a;
    asm("{ .reg .u64 t; cvta.to.shared.u64 t, %1; cvt.u32.u64 %0, t; }" : "=r"(a) : "l"(p));
    return a;
}
__device__ __forceinline__ void cp16(uint32_t dst, const void* src) {
    asm volatile("cp.async.cg.shared.global [%0], [%1], 16;" :: "r"(dst), "l"(src) : "memory");
}
#define CP_COMMIT() asm volatile("cp.async.commit_group;" ::: "memory")
#define CP_WAIT(n)  asm volatile("cp.async.wait_group %0;" :: "n"(n) : "memory")

__device__ __forceinline__ void ldsm_x4(uint32_t* r, uint32_t addr) {
    asm volatile("ldmatrix.sync.aligned.m8n8.x4.shared.b16 {%0,%1,%2,%3}, [%4];"
        : "=r"(r[0]), "=r"(r[1]), "=r"(r[2]), "=r"(r[3]) : "r"(addr));
}
__device__ __forceinline__ void mma_f16(float* d, const uint32_t* a, uint32_t b0, uint32_t b1) {
    asm volatile("mma.sync.aligned.m16n8k16.row.col.f32.f16.f16.f32 "
        "{%0,%1,%2,%3}, {%4,%5,%6,%7}, {%8,%9}, {%0,%1,%2,%3};"
        : "+f"(d[0]), "+f"(d[1]), "+f"(d[2]), "+f"(d[3])
        : "r"(a[0]), "r"(a[1]), "r"(a[2]), "r"(a[3]), "r"(b0), "r"(b1));
}
__device__ __forceinline__ void wait_cnt(const unsigned* p, unsigned target) {
    unsigned v;
    do {
        asm volatile("ld.acquire.gpu.global.u32 %0, [%1];" : "=r"(v) : "l"(p) : "memory");
    } while (v < target);
}
__device__ __forceinline__ float sigm(float x) { return 1.f / (1.f + __expf(-x)); }
__device__ __forceinline__ float tanh_f(float x) { return 1.f - 2.f / (1.f + __expf(2.f * x)); }

// ---- static device scratch ----
__device__ __align__(16) char g_Uimg[(size_t)128 * 16 * 16384];      // [c][chunk] 16KB fp16
__device__ __align__(16) char g_Wimg[(size_t)4 * 128 * 16384];       // [l][c] 16KB fp16
__device__ __align__(16) char g_xpimg[(size_t)TT * 32768];           // [t] fp16 hi only
__device__ __align__(16) char g_hinimg[(size_t)3 * 32768];           // [l] fp16 hi only
__device__ __align__(16) char g_hximg[(size_t)16 * 16384];           // [chunk] hi@0 lo@8192
__device__ float g_h[L][BATCH][H];
__device__ float g_c[L][BATCH][H];
__device__ float g_ugemm[BATCH][JTOT];
__device__ unsigned g_cntA3;
__device__ __align__(128) unsigned g_grp[8][32];    // distributed ARRIVAL counters
__device__ unsigned g_root = 0;
__device__ volatile unsigned g_gen = 0;             // single broadcast poll line

// ---- hierarchical grid barrier: distributed arrivals, single-line poll ----
__device__ __forceinline__ void grid_sync(int c)
{
    __syncthreads();
    if (threadIdx.x == 0) {
        unsigned g = g_gen;
        __threadfence();                                  // release
        if (atomicAdd(&g_grp[c >> 4][0], 1u) == 15u) {    // group of 16 CTAs
            g_grp[c >> 4][0] = 0;                         // safe: group won't re-arrive until gen flips
            if (atomicAdd(&g_root, 1u) == 7u) {           // 8 groups
                g_root = 0;
                __threadfence();
                g_gen = g + 1u;
            } else {
                while (g_gen == g) { }
            }
        } else {
            while (g_gen == g) { }
        }
        __threadfence();                                  // acquire
    }
    __syncthreads();
}

// ---- prep kernels (merged: U blocks 0..2047, W blocks 2048..2559) ----
__global__ void prep_all(const float* __restrict__ U, const float* __restrict__ W)
{
    if (blockIdx.x < 2048) {
        int blk = blockIdx.x;                 // c*16 + chunk
        int c = blk >> 4, chunk = blk & 15;
        char* dst = g_Uimg + (size_t)blk * 16384;
        for (int i = threadIdx.x; i < 1024; i += 256) {
            int r = i >> 4, s8 = i & 15;
            const float* src = U + ((size_t)(c * 64 + r)) * LH + chunk * 128 + s8 * 8;
            __half hv[8];
            #pragma unroll
            for (int j = 0; j < 8; ++j) hv[j] = __float2half_rn(src[j]);
            unsigned byte = SWZ((unsigned)((r >> 3) * 1024 + (s8 >> 3) * 8192 +
                                           (r & 7) * 128 + (s8 & 7) * 16));
            *(uint4*)(dst + byte) = *(uint4*)hv;
        }
    } else {
        int blk = blockIdx.x - 2048;          // l*128 + c
        int l = blk >> 7, c = blk & 127;
        char* dst = g_Wimg + (size_t)blk * 16384;
        for (int i = threadIdx.x; i < 1024; i += 256) {
            int r = i >> 6, s8 = i & 63;
            int q = r >> 2, ms = r & 3;
            int wrow = q * 512 + c * 4 + ms;
            const float* src = W + ((size_t)(l * G4 + wrow)) * H + s8 * 8;
            __half hv[8];
            #pragma unroll
            for (int j = 0; j < 8; ++j) hv[j] = __float2half_rn(src[j]);
            unsigned byte = SWZ((unsigned)((r >> 3) * 1024 + (s8 >> 3) * 2048 +
                                           (r & 7) * 128 + (s8 & 7) * 16));
            *(uint4*)(dst + byte) = *(uint4*)hv;
        }
    }
}

__global__ void xp_kernel(const float* __restrict__ x,
                          const float* __restrict__ lin_w,
                          const float* __restrict__ lin_b,
                          const float* __restrict__ mask_w)
{
    __shared__ float xs[16][128];
    int tb0 = blockIdx.x * 16;
    int tid = threadIdx.x;
    #pragma unroll
    for (int r = 0; r < 8; ++r) {
        int e = r * 256 + tid;
        xs[e >> 7][e & 127] = x[(size_t)(tb0 + (e >> 7)) * 128 + (e & 127)];
    }
    __syncthreads();
    int h0 = tid, h1 = tid + 256;
    const float* w0 = lin_w + (size_t)h0 * 128;
    const float* w1 = lin_w + (size_t)h1 * 128;
    float acc0[16], acc1[16];
    #pragma unroll
    for (int p = 0; p < 16; ++p) { acc0[p] = 0.f; acc1[p] = 0.f; }
    for (int i = 0; i < 128; i += 4) {
        float4 a = *(const float4*)(w0 + i);
        float4 b = *(const float4*)(w1 + i);
        #pragma unroll
        for (int p = 0; p < 16; ++p) {
            float4 xv = *(const float4*)&xs[p][i];
            acc0[p] += a.x * xv.x + a.y * xv.y + a.z * xv.z + a.w * xv.w;
            acc1[p] += b.x * xv.x + b.y * xv.y + b.z * xv.z + b.w * xv.w;
        }
    }
    float b0 = lin_b[h0], b1 = lin_b[h1];
    #pragma unroll
    for (int p = 0; p < 16; ++p) {
        int tb = tb0 + p;
        int tt = tb >> 5, bb = tb & 31;
        char* base = g_xpimg + (size_t)tt * 32768;
        #pragma unroll
        for (int cc = 0; cc < 2; ++cc) {
            int hh = cc ? h1 : h0;
            float v = ((cc ? acc1[p] : acc0[p]) + (cc ? b1 : b0)) *
                      mask_w[(size_t)bb * H + hh];
            __half hb = __float2half_rn(v);
            int seg = hh >> 3;
            unsigned byte = SWZ((unsigned)((bb >> 3) * 1024 + (seg >> 3) * 4096 +
                                           (bb & 7) * 128 + (seg & 7) * 16 + (hh & 7) * 2));
            *(__half*)(base + byte) = hb;
        }
    }
}

__global__ void init_hc(const float* __restrict__ h0, const float* __restrict__ c0)
{
    if (blockIdx.x == 0 && threadIdx.x == 0) { g_cntA3 = 0; g_root = 0; }
    if (blockIdx.x == 0 && threadIdx.x < 8) g_grp[threadIdx.x][0] = 0u;
    float* hp = &g_h[0][0][0];
    float* cp = &g_c[0][0][0];
    for (int i = blockIdx.x * blockDim.x + threadIdx.x; i < L * BATCH * H;
         i += gridDim.x * blockDim.x)
        { hp[i] = h0[i]; cp[i] = c0[i]; }
}

// ---- persistent kernel ----
// dyn SMEM: Ubuf 4x16K @0..64K ; hxbuf 4x16K @65536..131072 ; W resident 4x16K @131072..196608
// C-phase: inp (hi only, 32K) @0..32K (reuses Ubuf region, time-separated)
#define SMEM_DYN (196608 + 1024)

__global__ void __launch_bounds__(NTHR, 1)
rnn_kernel(const float* __restrict__ G,
           const float* __restrict__ mask_u,
           const float* __restrict__ mask_w,
           float* __restrict__ out)
{
    extern __shared__ char smc_raw[];
    __shared__ float redA[16];
    __shared__ float ghA;
    __shared__ float sm_g[16][33];
    __shared__ float red[4][16][33];

    const int c    = blockIdx.x;
    const int tid  = threadIdx.x;
    const int wid  = tid >> 5;
    const int lane = tid & 31;

    uint32_t sbr = smem_u32(smc_raw);
    uint32_t sb  = (sbr + 1023u) & ~1023u;

    // A: CTA = (layer, batch)
    const int al  = c & 3;
    const int abt = c >> 2;
    // B: warp = 4 J strips x 4 batch strips
    const int rs = wid >> 2;
    const int cs = wid & 3;
    // C: warp = (K split, batch strip); thread = (row r16, batch cb)
    const int ks = wid >> 2;
    const int ns = wid & 3;
    const int cb   = wid * 2 + (lane & 1);
    const int r16  = lane >> 1;
    const int q    = r16 >> 2;
    const int ms   = r16 & 3;
    const int mg   = c * 4 + ms;
    const int crow = q * 512 + mg;

    // hoisted per-thread constants
    const float Gv   = G[al * H + tid];
    const float muv  = mask_u[((size_t)(al * BATCH + abt)) * H + tid];
    float mwv[3];
    #pragma unroll
    for (int l = 0; l < 3; ++l)
        mwv[l] = mask_w[((size_t)((l + 1) * BATCH + cb)) * H + mg];

    float* out_h = out;
    float* out_c = out + L * BATCH * H;
    float* out_g = out + 2 * L * BATCH * H;

    // A work: gate + gated-masked hidden -> hx fp16 hi/lo image
    auto do_A = [&](int t_out) {
        float hm = g_h[al][abt][tid] * muv;
        float s  = hm * Gv;
        #pragma unroll
        for (int o = 16; o; o >>= 1) s += __shfl_xor_sync(~0u, s, o);
        if (lane == 0) redA[wid] = s;
        __syncthreads();
        if (tid == 0) {
            float ss = 0.f;
            #pragma unroll
            for (int r = 0; r < 16; ++r) ss += redA[r];
            float gh = sigm(ss);
            ghA = gh;
            out_g[(size_t)(al * BATCH + abt) * TT + t_out] = gh;
        }
        __syncthreads();
        float v = ghA * hm;
        __half hb = __float2half_rn(v);
        __half lb = __float2half_rn(v - __half2float(hb));
        int kg = al * 512 + tid;
        int chunk = kg >> 7, kl = kg & 127, seg = kl >> 3;
        unsigned byte = SWZ((unsigned)((abt >> 3) * 1024 + (seg >> 3) * 4096 +
                                       (abt & 7) * 128 + (seg & 7) * 16 + (kl & 7) * 2));
        char* base = g_hximg + (size_t)chunk * 16384;
        *(__half*)(base + byte) = hb;
        *(__half*)(base + 8192 + byte) = lb;
        if (al == 3) {
            __syncthreads();
            if (tid == 0) {
                __threadfence();
                atomicAdd(&g_cntA3, 1u);
            }
        }
    };

    // load resident W (all 4 layers, 64KB) into SMEM @131072
    {
        const char* wsrc = g_Wimg;
        #pragma unroll
        for (int i = 0; i < 8; ++i) {
            int idx = i * 512 + tid;               // 0..4095 (layer = idx>>10)
            int l = idx >> 10, off = idx & 1023;
            cp16(sb + 131072 + l * 16384 + off * 16,
                 wsrc + ((size_t)(l * 128 + c)) * 16384 + off * 16);
        }
        CP_COMMIT();
    }

    // peel: A for t=0, drain W load, then one grid sync before B(0)
    do_A(0);
    CP_WAIT(0);
    grid_sync(c);

    for (int t = 0; t < TT; ++t) {
        // layer-3 A for step t
        if (t >= 1 && al == 3) do_A(t);

        // ===== B: U-GEMM (fp16, 2 terms), 4-buffer pipeline, 1 sync per chunk =====
        {
            float dh[4] = {0.f, 0.f, 0.f, 0.f};
            float dl[4] = {0.f, 0.f, 0.f, 0.f};

            auto stageB = [&](int ck) {
                if (ck == 12) wait_cnt(&g_cntA3, 32u * (unsigned)(t + 1));
                int buf = ck & 3;
                const char* us = g_Uimg + (size_t)(c * 16 + ck) * 16384;
                #pragma unroll
                for (int i = 0; i < 2; ++i) {
                    int idx = i * 512 + tid;
                    cp16(sb + buf * 16384 + idx * 16, us + idx * 16);
                }
                const char* hs = g_hximg + (size_t)ck * 16384;
                #pragma unroll
                for (int i = 0; i < 2; ++i) {
                    int idx = i * 512 + tid;
                    cp16(sb + 65536 + buf * 16384 + idx * 16, hs + idx * 16);
                }
            };

            stageB(0); CP_COMMIT();
            stageB(1); CP_COMMIT();
            for (int ck = 0; ck < 16; ++ck) {
                if (ck + 2 < 16) { stageB(ck + 2); CP_COMMIT(); }
                if (ck <= 13)      { CP_WAIT(2); }
                else if (ck == 14) { CP_WAIT(1); }
                else               { CP_WAIT(0); }
                __syncthreads();

                uint32_t au  = sb + (ck & 3) * 16384;
                uint32_t buh = sb + 65536 + (ck & 3) * 16384, bul = buh + 8192;
                #pragma unroll
                for (int g = 0; g < 4; ++g) {
                    uint32_t baddr = (g >> 1) * 4096 + (cs * 8 + (lane & 7)) * 128 +
                                     (g & 1) * 64 + (lane >> 3) * 16;
                    uint32_t bh[4], bl_[4];
                    ldsm_x4(bh,  buh + SWZ(baddr));
                    ldsm_x4(bl_, bul + SWZ(baddr));
                    #pragma unroll
                    for (int sh = 0; sh < 2; ++sh) {
                        int s = g * 2 + sh;
                        uint32_t aaddr = (s >> 2) * 8192 + (rs * 16 + (lane & 15)) * 128 +
                                         (s & 3) * 32 + (lane >> 4) * 16;
                        uint32_t ah[4];
                        ldsm_x4(ah, au + SWZ(aaddr));
                        mma_f16(dh, ah, bh[2 * sh],  bh[2 * sh + 1]);
                        mma_f16(dl, ah, bl_[2 * sh], bl_[2 * sh + 1]);
                    }
                }
            }
            __syncthreads();
            int m = c * 64 + rs * 16 + (lane >> 2);
            int n = cs * 8 + (lane & 3) * 2;
            g_ugemm[n][m]         = dh[0] + dl[0];
            g_ugemm[n + 1][m]     = dh[1] + dl[1];
            g_ugemm[n][m + 8]     = dh[2] + dl[2];
            g_ugemm[n + 1][m + 8] = dh[3] + dl[3];
        }
        grid_sync(c);

        // ===== C: serial layer chain, W resident, inp fp16 hi-only =====
        #pragma unroll
        for (int l = 0; l < 4; ++l) {
            const char* isrc = (l == 0) ? (g_xpimg + (size_t)t * 32768)
                                        : (g_hinimg + (size_t)(l - 1) * 32768);
            #pragma unroll
            for (int i = 0; i < 4; ++i) {
                int idx = i * 512 + tid;
                cp16(sb + idx * 16, isrc + idx * 16);
            }
            CP_COMMIT();

            // embedded A for layer l-1, step t+1 (overlapped with cp.async)
            if (l >= 1 && t != TT - 1 && al == l - 1) do_A(t + 1);

            CP_WAIT(0);
            __syncthreads();

            float ug = g_ugemm[cb][l * G4 + crow];

            float ddh[4] = {0.f, 0.f, 0.f, 0.f};
            uint32_t wres = sb + 131072 + l * 16384;
            uint32_t ih = sb;
            #pragma unroll
            for (int gg = 0; gg < 4; ++gg) {
                uint32_t baddr = (ks * 2 + (gg >> 1)) * 4096 + (ns * 8 + (lane & 7)) * 128 +
                                 (gg & 1) * 64 + (lane >> 3) * 16;
                uint32_t bh[4];
                ldsm_x4(bh, ih + SWZ(baddr));
                #pragma unroll
                for (int jh = 0; jh < 2; ++jh) {
                    int s = ks * 8 + gg * 2 + jh;
                    uint32_t aaddr = (s >> 2) * 2048 + (lane & 15) * 128 +
                                     (s & 3) * 32 + (lane >> 4) * 16;
                    uint32_t ah[4];
                    ldsm_x4(ah, wres + SWZ(aaddr));
                    mma_f16(ddh, ah, bh[2 * jh], bh[2 * jh + 1]);
                }
            }
            {
                int m0 = lane >> 2, n0 = ns * 8 + (lane & 3) * 2;
                red[ks][m0][n0]         = ddh[0];
                red[ks][m0][n0 + 1]     = ddh[1];
                red[ks][m0 + 8][n0]     = ddh[2];
                red[ks][m0 + 8][n0 + 1] = ddh[3];
            }
            __syncthreads();

            float a = red[0][r16][cb] + red[1][r16][cb] +
                      red[2][r16][cb] + red[3][r16][cb] + ug;
            float act = (q == 2) ? tanh_f(a) : sigm(a);
            sm_g[r16][cb] = act;
            __syncthreads();
            if (q == 0) {
                float gf  = sm_g[4 + ms][cb];
                float gg_ = sm_g[8 + ms][cb];
                float go  = sm_g[12 + ms][cb];
                float cold = g_c[l][cb][mg];
                float cn = gf * cold + act * gg_;
                float hy = go * tanh_f(cn);
                g_c[l][cb][mg] = cn;
                g_h[l][cb][mg] = hy;
                if (l < 3) {
                    float hv = hy * mwv[l];
                    __half hb = __float2half_rn(hv);
                    int seg = mg >> 3;
                    unsigned byte = SWZ((unsigned)((cb >> 3) * 1024 + (seg >> 3) * 4096 +
                                                   (cb & 7) * 128 + (seg & 7) * 16 + (mg & 7) * 2));
                    *(__half*)(g_hinimg + (size_t)l * 32768 + byte) = hb;
                }
            }
            grid_sync(c);
        }
    }

    const float* hp = &g_h[0][0][0];
    const float* cp = &g_c[0][0][0];
    for (int idx = c * NTHR + tid; idx < L * BATCH * H; idx += NCTA * NTHR) {
        out_h[idx] = hp[idx];
        out_c[idx] = cp[idx];
    }
}

// ---- launch ----
extern "C" void kernel_launch(void* const* d_in, const int* in_sizes, int n_in,
                              void* d_out, int out_size)
{
    const float* x      = (const float*)d_in[0];
    const float* lin_w  = (const float*)d_in[1];
    const float* lin_b  = (const float*)d_in[2];
    const float* W      = (const float*)d_in[3];
    const float* U      = (const float*)d_in[4];
    const float* G      = (const float*)d_in[5];
    const float* mask_u = (const float*)d_in[6];
    const float* mask_w = (const float*)d_in[7];
    const float* h0     = (const float*)d_in[8];
    const float* c0     = (const float*)d_in[9];
    float* out = (float*)d_out;
    (void)in_sizes; (void)n_in; (void)out_size;

    prep_all<<<2048 + 512, 256>>>(U, W);
    xp_kernel<<<(TT * BATCH) / 16, 256>>>(x, lin_w, lin_b, mask_w);
    init_hc<<<64, 256>>>(h0, c0);

    cudaFuncSetAttribute(rnn_kernel, cudaFuncAttributeMaxDynamicSharedMemorySize, SMEM_DYN);
    rnn_kernel<<<NCTA, NTHR, SMEM_DYN>>>(G, mask_u, mask_w, out);
}

// round 15
// speedup vs baseline: 1.0147x; 1.0147x over previous
#include <cuda_runtime.h>
#include <cuda_fp16.h>
#include <math.h>
#include <stdint.h>

#define L     4
#define H     512
#define BATCH 32
#define TT    1024
#define G4    2048
#define LH    2048
#define JTOT  8192
#define NCTA  128
#define NTHR  512

#define SWZ(o) ((unsigned)(o) ^ (((unsigned)(o) >> 3) & 0x70u))

// ---- PTX helpers (base-target features only) ----
__device__ __forceinline__ uint32_t smem_u32(const void* p) {
    uint32_t a;
    asm("{ .reg .u64 t; cvta.to.shared.u64 t, %1; cvt.u32.u64 %0, t; }" : "=r"(a) : "l"(p));
    return a;
}
__device__ __forceinline__ void cp16(uint32_t dst, const void* src) {
    asm volatile("cp.async.cg.shared.global [%0], [%1], 16;" :: "r"(dst), "l"(src) : "memory");
}
#define CP_COMMIT() asm volatile("cp.async.commit_group;" ::: "memory")
#define CP_WAIT(n)  asm volatile("cp.async.wait_group %0;" :: "n"(n) : "memory")

__device__ __forceinline__ void ldsm_x4(uint32_t* r, uint32_t addr) {
    asm volatile("ldmatrix.sync.aligned.m8n8.x4.shared.b16 {%0,%1,%2,%3}, [%4];"
        : "=r"(r[0]), "=r"(r[1]), "=r"(r[2]), "=r"(r[3]) : "r"(addr));
}
__device__ __forceinline__ void mma_f16(float* d, const uint32_t* a, uint32_t b0, uint32_t b1) {
    asm volatile("mma.sync.aligned.m16n8k16.row.col.f32.f16.f16.f32 "
        "{%0,%1,%2,%3}, {%4,%5,%6,%7}, {%8,%9}, {%0,%1,%2,%3};"
        : "+f"(d[0]), "+f"(d[1]), "+f"(d[2]), "+f"(d[3])
        : "r"(a[0]), "r"(a[1]), "r"(a[2]), "r"(a[3]), "r"(b0), "r"(b1));
}
__device__ __forceinline__ void wait_cnt(const unsigned* p, unsigned target) {
    unsigned v;
    do {
        asm volatile("ld.acquire.gpu.global.u32 %0, [%1];" : "=r"(v) : "l"(p) : "memory");
    } while (v < target);
}
__device__ __forceinline__ float sigm(float x) { return 1.f / (1.f + __expf(-x)); }
__device__ __forceinline__ float tanh_f(float x) { return 1.f - 2.f / (1.f + __expf(2.f * x)); }

// ---- static device scratch ----
__device__ __align__(16) char g_Uimg[(size_t)128 * 16 * 16384];      // [c][chunk] 16KB fp16
__device__ __align__(16) char g_Wimg[(size_t)4 * 128 * 16384];       // [l][c] 16KB fp16
__device__ __align__(16) char g_xpimg[(size_t)TT * 32768];           // [t] fp16 hi only
__device__ __align__(16) char g_hinimg[(size_t)3 * 32768];           // [l] fp16 hi only
__device__ __align__(16) char g_hximg[(size_t)16 * 16384];           // [chunk] hi@0 lo@8192
__device__ float g_h[L][BATCH][H];
__device__ float g_c[L][BATCH][H];
__device__ float g_ugemm[BATCH][JTOT];
__device__ unsigned g_cntA3;
__device__ unsigned g_cnt = 0;
__device__ volatile unsigned g_gen = 0;

// ---- software grid barrier (R6/R13-proven single hot line; FROZEN) ----
__device__ __forceinline__ void grid_sync()
{
    __syncthreads();
    if (threadIdx.x == 0) {
        unsigned g = g_gen;
        __threadfence();
        if (atomicAdd(&g_cnt, 1u) == NCTA - 1u) {
            g_cnt = 0;
            __threadfence();
            g_gen = g + 1u;
        } else {
            while (g_gen == g) { }
        }
        __threadfence();
    }
    __syncthreads();
}

// ---- prep kernels (merged: U blocks 0..2047, W blocks 2048..2559) ----
__global__ void prep_all(const float* __restrict__ U, const float* __restrict__ W)
{
    if (blockIdx.x < 2048) {
        int blk = blockIdx.x;                 // c*16 + chunk
        int c = blk >> 4, chunk = blk & 15;
        char* dst = g_Uimg + (size_t)blk * 16384;
        for (int i = threadIdx.x; i < 1024; i += 256) {
            int r = i >> 4, s8 = i & 15;
            const float* src = U + ((size_t)(c * 64 + r)) * LH + chunk * 128 + s8 * 8;
            __half hv[8];
            #pragma unroll
            for (int j = 0; j < 8; ++j) hv[j] = __float2half_rn(src[j]);
            unsigned byte = SWZ((unsigned)((r >> 3) * 1024 + (s8 >> 3) * 8192 +
                                           (r & 7) * 128 + (s8 & 7) * 16));
            *(uint4*)(dst + byte) = *(uint4*)hv;
        }
    } else {
        int blk = blockIdx.x - 2048;          // l*128 + c
        int l = blk >> 7, c = blk & 127;
        char* dst = g_Wimg + (size_t)blk * 16384;
        for (int i = threadIdx.x; i < 1024; i += 256) {
            int r = i >> 6, s8 = i & 63;
            int q = r >> 2, ms = r & 3;
            int wrow = q * 512 + c * 4 + ms;
            const float* src = W + ((size_t)(l * G4 + wrow)) * H + s8 * 8;
            __half hv[8];
            #pragma unroll
            for (int j = 0; j < 8; ++j) hv[j] = __float2half_rn(src[j]);
            unsigned byte = SWZ((unsigned)((r >> 3) * 1024 + (s8 >> 3) * 2048 +
                                           (r & 7) * 128 + (s8 & 7) * 16));
            *(uint4*)(dst + byte) = *(uint4*)hv;
        }
    }
}

__global__ void xp_kernel(const float* __restrict__ x,
                          const float* __restrict__ lin_w,
                          const float* __restrict__ lin_b,
                          const float* __restrict__ mask_w)
{
    __shared__ float xs[16][128];
    int tb0 = blockIdx.x * 16;
    int tid = threadIdx.x;
    #pragma unroll
    for (int r = 0; r < 8; ++r) {
        int e = r * 256 + tid;
        xs[e >> 7][e & 127] = x[(size_t)(tb0 + (e >> 7)) * 128 + (e & 127)];
    }
    __syncthreads();
    int h0 = tid, h1 = tid + 256;
    const float* w0 = lin_w + (size_t)h0 * 128;
    const float* w1 = lin_w + (size_t)h1 * 128;
    float acc0[16], acc1[16];
    #pragma unroll
    for (int p = 0; p < 16; ++p) { acc0[p] = 0.f; acc1[p] = 0.f; }
    for (int i = 0; i < 128; i += 4) {
        float4 a = *(const float4*)(w0 + i);
        float4 b = *(const float4*)(w1 + i);
        #pragma unroll
        for (int p = 0; p < 16; ++p) {
            float4 xv = *(const float4*)&xs[p][i];
            acc0[p] += a.x * xv.x + a.y * xv.y + a.z * xv.z + a.w * xv.w;
            acc1[p] += b.x * xv.x + b.y * xv.y + b.z * xv.z + b.w * xv.w;
        }
    }
    float b0 = lin_b[h0], b1 = lin_b[h1];
    #pragma unroll
    for (int p = 0; p < 16; ++p) {
        int tb = tb0 + p;
        int tt = tb >> 5, bb = tb & 31;
        char* base = g_xpimg + (size_t)tt * 32768;
        #pragma unroll
        for (int cc = 0; cc < 2; ++cc) {
            int hh = cc ? h1 : h0;
            float v = ((cc ? acc1[p] : acc0[p]) + (cc ? b1 : b0)) *
                      mask_w[(size_t)bb * H + hh];
            __half hb = __float2half_rn(v);
            int seg = hh >> 3;
            unsigned byte = SWZ((unsigned)((bb >> 3) * 1024 + (seg >> 3) * 4096 +
                                           (bb & 7) * 128 + (seg & 7) * 16 + (hh & 7) * 2));
            *(__half*)(base + byte) = hb;
        }
    }
}

__global__ void init_hc(const float* __restrict__ h0, const float* __restrict__ c0)
{
    if (blockIdx.x == 0 && threadIdx.x == 0) g_cntA3 = 0;
    float* hp = &g_h[0][0][0];
    float* cp = &g_c[0][0][0];
    for (int i = blockIdx.x * blockDim.x + threadIdx.x; i < L * BATCH * H;
         i += gridDim.x * blockDim.x)
        { hp[i] = h0[i]; cp[i] = c0[i]; }
}

// ---- persistent kernel ----
// dyn SMEM: Ubuf 4x16K @0..64K ; hxbuf 4x16K @65536..131072 ; W resident 4x16K @131072..196608
// C-phase: inp (hi only, 32K) @0..32K (reuses Ubuf region, time-separated)
#define SMEM_DYN (196608 + 1024)

__global__ void __launch_bounds__(NTHR, 1)
rnn_kernel(const float* __restrict__ G,
           const float* __restrict__ mask_u,
           const float* __restrict__ mask_w,
           float* __restrict__ out)
{
    extern __shared__ char smc_raw[];
    __shared__ float redA[16];
    __shared__ float ghA;
    __shared__ float red[4][16][33];

    const int c    = blockIdx.x;
    const int tid  = threadIdx.x;
    const int wid  = tid >> 5;
    const int lane = tid & 31;

    uint32_t sbr = smem_u32(smc_raw);
    uint32_t sb  = (sbr + 1023u) & ~1023u;

    // A: CTA = (layer, batch)
    const int al  = c & 3;
    const int abt = c >> 2;
    // B: warp = 4 J strips x 4 batch strips
    const int rs = wid >> 2;
    const int cs = wid & 3;
    // C: warp = (K split, batch strip); thread = (row r16, batch cb)
    const int ks = wid >> 2;
    const int ns = wid & 3;
    const int cb   = wid * 2 + (lane & 1);
    const int r16  = lane >> 1;
    const int q    = r16 >> 2;
    const int ms   = r16 & 3;
    const int mg   = c * 4 + ms;

    // hoisted per-thread constants
    const float Gv   = G[al * H + tid];
    const float muv  = mask_u[((size_t)(al * BATCH + abt)) * H + tid];
    float mwv[3];
    #pragma unroll
    for (int l = 0; l < 3; ++l)
        mwv[l] = mask_w[((size_t)((l + 1) * BATCH + cb)) * H + mg];

    float* out_h = out;
    float* out_c = out + L * BATCH * H;
    float* out_g = out + 2 * L * BATCH * H;

    // A work: gate + gated-masked hidden -> hx fp16 hi/lo image
    auto do_A = [&](int t_out) {
        float hm = g_h[al][abt][tid] * muv;
        float s  = hm * Gv;
        #pragma unroll
        for (int o = 16; o; o >>= 1) s += __shfl_xor_sync(~0u, s, o);
        if (lane == 0) redA[wid] = s;
        __syncthreads();
        if (tid == 0) {
            float ss = 0.f;
            #pragma unroll
            for (int r = 0; r < 16; ++r) ss += redA[r];
            float gh = sigm(ss);
            ghA = gh;
            out_g[(size_t)(al * BATCH + abt) * TT + t_out] = gh;
        }
        __syncthreads();
        float v = ghA * hm;
        __half hb = __float2half_rn(v);
        __half lb = __float2half_rn(v - __half2float(hb));
        int kg = al * 512 + tid;
        int chunk = kg >> 7, kl = kg & 127, seg = kl >> 3;
        unsigned byte = SWZ((unsigned)((abt >> 3) * 1024 + (seg >> 3) * 4096 +
                                       (abt & 7) * 128 + (seg & 7) * 16 + (kl & 7) * 2));
        char* base = g_hximg + (size_t)chunk * 16384;
        *(__half*)(base + byte) = hb;
        *(__half*)(base + 8192 + byte) = lb;
        if (al == 3) {
            __syncthreads();
            if (tid == 0) {
                __threadfence();
                atomicAdd(&g_cntA3, 1u);
            }
        }
    };

    // load resident W (all 4 layers, 64KB) into SMEM @131072
    {
        const char* wsrc = g_Wimg;
        #pragma unroll
        for (int i = 0; i < 8; ++i) {
            int idx = i * 512 + tid;               // 0..4095 (layer = idx>>10)
            int l = idx >> 10, off = idx & 1023;
            cp16(sb + 131072 + l * 16384 + off * 16,
                 wsrc + ((size_t)(l * 128 + c)) * 16384 + off * 16);
        }
        CP_COMMIT();
    }

    // peel: A for t=0, drain W load, then one grid sync before B(0)
    do_A(0);
    CP_WAIT(0);
    grid_sync();

    for (int t = 0; t < TT; ++t) {
        // layer-3 A for step t
        if (t >= 1 && al == 3) do_A(t);

        // ===== B: U-GEMM (fp16, 2 terms), 4-buffer pipeline, 1 sync per chunk =====
        {
            float dh[4] = {0.f, 0.f, 0.f, 0.f};
            float dl[4] = {0.f, 0.f, 0.f, 0.f};

            auto stageB = [&](int ck) {
                if (ck == 12) wait_cnt(&g_cntA3, 32u * (unsigned)(t + 1));
                int buf = ck & 3;
                const char* us = g_Uimg + (size_t)(c * 16 + ck) * 16384;
                #pragma unroll
                for (int i = 0; i < 2; ++i) {
                    int idx = i * 512 + tid;
                    cp16(sb + buf * 16384 + idx * 16, us + idx * 16);
                }
                const char* hs = g_hximg + (size_t)ck * 16384;
                #pragma unroll
                for (int i = 0; i < 2; ++i) {
                    int idx = i * 512 + tid;
                    cp16(sb + 65536 + buf * 16384 + idx * 16, hs + idx * 16);
                }
            };

            stageB(0); CP_COMMIT();
            stageB(1); CP_COMMIT();
            for (int ck = 0; ck < 16; ++ck) {
                if (ck + 2 < 16) { stageB(ck + 2); CP_COMMIT(); }
                if (ck <= 13)      { CP_WAIT(2); }
                else if (ck == 14) { CP_WAIT(1); }
                else               { CP_WAIT(0); }
                __syncthreads();

                uint32_t au  = sb + (ck & 3) * 16384;
                uint32_t buh = sb + 65536 + (ck & 3) * 16384, bul = buh + 8192;
                #pragma unroll
                for (int g = 0; g < 4; ++g) {
                    uint32_t baddr = (g >> 1) * 4096 + (cs * 8 + (lane & 7)) * 128 +
                                     (g & 1) * 64 + (lane >> 3) * 16;
                    uint32_t bh[4], bl_[4];
                    ldsm_x4(bh,  buh + SWZ(baddr));
                    ldsm_x4(bl_, bul + SWZ(baddr));
                    #pragma unroll
                    for (int sh = 0; sh < 2; ++sh) {
                        int s = g * 2 + sh;
                        uint32_t aaddr = (s >> 2) * 8192 + (rs * 16 + (lane & 15)) * 128 +
                                         (s & 3) * 32 + (lane >> 4) * 16;
                        uint32_t ah[4];
                        ldsm_x4(ah, au + SWZ(aaddr));
                        mma_f16(dh, ah, bh[2 * sh],  bh[2 * sh + 1]);
                        mma_f16(dl, ah, bl_[2 * sh], bl_[2 * sh + 1]);
                    }
                }
            }
            __syncthreads();
            int m = c * 64 + rs * 16 + (lane >> 2);
            int n = cs * 8 + (lane & 3) * 2;
            g_ugemm[n][m]         = dh[0] + dl[0];
            g_ugemm[n + 1][m]     = dh[1] + dl[1];
            g_ugemm[n][m + 8]     = dh[2] + dl[2];
            g_ugemm[n + 1][m + 8] = dh[3] + dl[3];
        }
        grid_sync();

        // ===== C: serial layer chain, W resident, inp fp16 hi-only =====
        #pragma unroll
        for (int l = 0; l < 4; ++l) {
            const char* isrc = (l == 0) ? (g_xpimg + (size_t)t * 32768)
                                        : (g_hinimg + (size_t)(l - 1) * 32768);
            #pragma unroll
            for (int i = 0; i < 4; ++i) {
                int idx = i * 512 + tid;
                cp16(sb + idx * 16, isrc + idx * 16);
            }
            CP_COMMIT();

            // prefetch U-GEMM gate values for this layer's cell update (q==0 only);
            // issued before the staging wait so the L2 latency is hidden
            float ug_i = 0.f, ug_f = 0.f, ug_g = 0.f, ug_o = 0.f;
            if (q == 0) {
                const float* ub = &g_ugemm[cb][l * G4 + mg];
                ug_i = ub[0];
                ug_f = ub[512];
                ug_g = ub[1024];
                ug_o = ub[1536];
            }

            // embedded A for layer l-1, step t+1 (overlapped with cp.async)
            if (l >= 1 && t != TT - 1 && al == l - 1) do_A(t + 1);

            CP_WAIT(0);
            __syncthreads();

            float ddh[4] = {0.f, 0.f, 0.f, 0.f};
            uint32_t wres = sb + 131072 + l * 16384;
            uint32_t ih = sb;
            #pragma unroll
            for (int gg = 0; gg < 4; ++gg) {
                uint32_t baddr = (ks * 2 + (gg >> 1)) * 4096 + (ns * 8 + (lane & 7)) * 128 +
                                 (gg & 1) * 64 + (lane >> 3) * 16;
                uint32_t bh[4];
                ldsm_x4(bh, ih + SWZ(baddr));
                #pragma unroll
                for (int jh = 0; jh < 2; ++jh) {
                    int s = ks * 8 + gg * 2 + jh;
                    uint32_t aaddr = (s >> 2) * 2048 + (lane & 15) * 128 +
                                     (s & 3) * 32 + (lane >> 4) * 16;
                    uint32_t ah[4];
                    ldsm_x4(ah, wres + SWZ(aaddr));
                    mma_f16(ddh, ah, bh[2 * jh], bh[2 * jh + 1]);
                }
            }
            {
                int m0 = lane >> 2, n0 = ns * 8 + (lane & 3) * 2;
                red[ks][m0][n0]         = ddh[0];
                red[ks][m0][n0 + 1]     = ddh[1];
                red[ks][m0 + 8][n0]     = ddh[2];
                red[ks][m0 + 8][n0 + 1] = ddh[3];
            }
            __syncthreads();

            if (q == 0) {
                // q==0 threads own all 4 gate rows for (cb, mg): sum K-splits + U-term
                float ai = red[0][ms][cb] + red[1][ms][cb] +
                           red[2][ms][cb] + red[3][ms][cb] + ug_i;
                float af = red[0][4 + ms][cb] + red[1][4 + ms][cb] +
                           red[2][4 + ms][cb] + red[3][4 + ms][cb] + ug_f;
                float ag = red[0][8 + ms][cb] + red[1][8 + ms][cb] +
                           red[2][8 + ms][cb] + red[3][8 + ms][cb] + ug_g;
                float ao = red[0][12 + ms][cb] + red[1][12 + ms][cb] +
                           red[2][12 + ms][cb] + red[3][12 + ms][cb] + ug_o;
                float gi = sigm(ai);
                float gf = sigm(af);
                float gg_ = tanh_f(ag);
                float go = sigm(ao);
                float cold = g_c[l][cb][mg];
                float cn = gf * cold + gi * gg_;
                float hy = go * tanh_f(cn);
                g_c[l][cb][mg] = cn;
                g_h[l][cb][mg] = hy;
                if (l < 3) {
                    float hv = hy * mwv[l];
                    __half hb = __float2half_rn(hv);
                    int seg = mg >> 3;
                    unsigned byte = SWZ((unsigned)((cb >> 3) * 1024 + (seg >> 3) * 4096 +
                                                   (cb & 7) * 128 + (seg & 7) * 16 + (mg & 7) * 2));
                    *(__half*)(g_hinimg + (size_t)l * 32768 + byte) = hb;
                }
            }
            grid_sync();
        }
    }

    const float* hp = &g_h[0][0][0];
    const float* cp = &g_c[0][0][0];
    for (int idx = c * NTHR + tid; idx < L * BATCH * H; idx += NCTA * NTHR) {
        out_h[idx] = hp[idx];
        out_c[idx] = cp[idx];
    }
}

// ---- launch ----
extern "C" void kernel_launch(void* const* d_in, const int* in_sizes, int n_in,
                              void* d_out, int out_size)
{
    const float* x      = (const float*)d_in[0];
    const float* lin_w  = (const float*)d_in[1];
    const float* lin_b  = (const float*)d_in[2];
    const float* W      = (const float*)d_in[3];
    const float* U      = (const float*)d_in[4];
    const float* G      = (const float*)d_in[5];
    const float* mask_u = (const float*)d_in[6];
    const float* mask_w = (const float*)d_in[7];
    const float* h0     = (const float*)d_in[8];
    const float* c0     = (const float*)d_in[9];
    float* out = (float*)d_out;
    (void)in_sizes; (void)n_in; (void)out_size;

    prep_all<<<2048 + 512, 256>>>(U, W);
    xp_kernel<<<(TT * BATCH) / 16, 256>>>(x, lin_w, lin_b, mask_w);
    init_hc<<<64, 256>>>(h0, c0);

    cudaFuncSetAttribute(rnn_kernel, cudaFuncAttributeMaxDynamicSharedMemorySize, SMEM_DYN);
    rnn_kernel<<<NCTA, NTHR, SMEM_DYN>>>(G, mask_u, mask_w, out);
}

// round 16
// speedup vs baseline: 1.1485x; 1.1318x over previous
#include <cuda_runtime.h>
#include <cuda_fp16.h>
#include <math.h>
#include <stdint.h>

#define L     4
#define H     512
#define BATCH 32
#define TT    1024
#define G4    2048
#define LH    2048
#define JTOT  8192
#define NCTA  128
#define NTHR  512

#define SWZ(o) ((unsigned)(o) ^ (((unsigned)(o) >> 3) & 0x70u))

// ---- PTX helpers (base-target features only) ----
__device__ __forceinline__ uint32_t smem_u32(const void* p) {
    uint32_t a;
    asm("{ .reg .u64 t; cvta.to.shared.u64 t, %1; cvt.u32.u64 %0, t; }" : "=r"(a) : "l"(p));
    return a;
}
__device__ __forceinline__ void cp16(uint32_t dst, const void* src) {
    asm volatile("cp.async.cg.shared.global [%0], [%1], 16;" :: "r"(dst), "l"(src) : "memory");
}
#define CP_COMMIT() asm volatile("cp.async.commit_group;" ::: "memory")
#define CP_WAIT(n)  asm volatile("cp.async.wait_group %0;" :: "n"(n) : "memory")

__device__ __forceinline__ void ldsm_x4(uint32_t* r, uint32_t addr) {
    asm volatile("ldmatrix.sync.aligned.m8n8.x4.shared.b16 {%0,%1,%2,%3}, [%4];"
        : "=r"(r[0]), "=r"(r[1]), "=r"(r[2]), "=r"(r[3]) : "r"(addr));
}
__device__ __forceinline__ void mma_f16(float* d, const uint32_t* a, uint32_t b0, uint32_t b1) {
    asm volatile("mma.sync.aligned.m16n8k16.row.col.f32.f16.f16.f32 "
        "{%0,%1,%2,%3}, {%4,%5,%6,%7}, {%8,%9}, {%0,%1,%2,%3};"
        : "+f"(d[0]), "+f"(d[1]), "+f"(d[2]), "+f"(d[3])
        : "r"(a[0]), "r"(a[1]), "r"(a[2]), "r"(a[3]), "r"(b0), "r"(b1));
}
__device__ __forceinline__ void wait_cnt(const unsigned* p, unsigned target) {
    unsigned v;
    do {
        asm volatile("ld.acquire.gpu.u32 %0, [%1];" : "=r"(v) : "l"(p) : "memory");
    } while (v < target);
}
__device__ __forceinline__ float sigm(float x) { return 1.f / (1.f + __expf(-x)); }
__device__ __forceinline__ float tanh_f(float x) { return 1.f - 2.f / (1.f + __expf(2.f * x)); }

// ---- static device scratch ----
__device__ __align__(16) char g_Uimg[(size_t)128 * 16 * 16384];      // [c][chunk] 16KB fp16
__device__ __align__(16) char g_Wimg[(size_t)4 * 128 * 16384];       // [l][c] 16KB fp16
__device__ __align__(16) char g_xpimg[(size_t)TT * 32768];           // [t] fp16 hi only
__device__ __align__(16) char g_hinimg[(size_t)3 * 32768];           // [l] fp16 hi only
__device__ __align__(16) char g_hximg[(size_t)16 * 8192];            // [chunk] fp16 hi only
__device__ float g_h[L][BATCH][H];
__device__ float g_c[L][BATCH][H];
__device__ float g_ugemm[BATCH][JTOT];
__device__ unsigned g_cntA3;
__device__ unsigned g_cnt = 0;
__device__ volatile unsigned g_gen = 0;

// ---- software grid barrier (R6/R13-proven single hot line; FROZEN) ----
__device__ __forceinline__ void grid_sync()
{
    __syncthreads();
    if (threadIdx.x == 0) {
        unsigned g = g_gen;
        __threadfence();
        if (atomicAdd(&g_cnt, 1u) == NCTA - 1u) {
            g_cnt = 0;
            __threadfence();
            g_gen = g + 1u;
        } else {
            while (g_gen == g) { }
        }
        __threadfence();
    }
    __syncthreads();
}

// ---- prep kernels (merged: U blocks 0..2047, W blocks 2048..2559) ----
__global__ void prep_all(const float* __restrict__ U, const float* __restrict__ W)
{
    if (blockIdx.x < 2048) {
        int blk = blockIdx.x;                 // c*16 + chunk
        int c = blk >> 4, chunk = blk & 15;
        char* dst = g_Uimg + (size_t)blk * 16384;
        for (int i = threadIdx.x; i < 1024; i += 256) {
            int r = i >> 4, s8 = i & 15;
            const float* src = U + ((size_t)(c * 64 + r)) * LH + chunk * 128 + s8 * 8;
            __half hv[8];
            #pragma unroll
            for (int j = 0; j < 8; ++j) hv[j] = __float2half_rn(src[j]);
            unsigned byte = SWZ((unsigned)((r >> 3) * 1024 + (s8 >> 3) * 8192 +
                                           (r & 7) * 128 + (s8 & 7) * 16));
            *(uint4*)(dst + byte) = *(uint4*)hv;
        }
    } else {
        int blk = blockIdx.x - 2048;          // l*128 + c
        int l = blk >> 7, c = blk & 127;
        char* dst = g_Wimg + (size_t)blk * 16384;
        for (int i = threadIdx.x; i < 1024; i += 256) {
            int r = i >> 6, s8 = i & 63;
            int q = r >> 2, ms = r & 3;
            int wrow = q * 512 + c * 4 + ms;
            const float* src = W + ((size_t)(l * G4 + wrow)) * H + s8 * 8;
            __half hv[8];
            #pragma unroll
            for (int j = 0; j < 8; ++j) hv[j] = __float2half_rn(src[j]);
            unsigned byte = SWZ((unsigned)((r >> 3) * 1024 + (s8 >> 3) * 2048 +
                                           (r & 7) * 128 + (s8 & 7) * 16));
            *(uint4*)(dst + byte) = *(uint4*)hv;
        }
    }
}

__global__ void xp_kernel(const float* __restrict__ x,
                          const float* __restrict__ lin_w,
                          const float* __restrict__ lin_b,
                          const float* __restrict__ mask_w)
{
    __shared__ float xs[16][128];
    int tb0 = blockIdx.x * 16;
    int tid = threadIdx.x;
    #pragma unroll
    for (int r = 0; r < 8; ++r) {
        int e = r * 256 + tid;
        xs[e >> 7][e & 127] = x[(size_t)(tb0 + (e >> 7)) * 128 + (e & 127)];
    }
    __syncthreads();
    int h0 = tid, h1 = tid + 256;
    const float* w0 = lin_w + (size_t)h0 * 128;
    const float* w1 = lin_w + (size_t)h1 * 128;
    float acc0[16], acc1[16];
    #pragma unroll
    for (int p = 0; p < 16; ++p) { acc0[p] = 0.f; acc1[p] = 0.f; }
    for (int i = 0; i < 128; i += 4) {
        float4 a = *(const float4*)(w0 + i);
        float4 b = *(const float4*)(w1 + i);
        #pragma unroll
        for (int p = 0; p < 16; ++p) {
            float4 xv = *(const float4*)&xs[p][i];
            acc0[p] += a.x * xv.x + a.y * xv.y + a.z * xv.z + a.w * xv.w;
            acc1[p] += b.x * xv.x + b.y * xv.y + b.z * xv.z + b.w * xv.w;
        }
    }
    float b0 = lin_b[h0], b1 = lin_b[h1];
    #pragma unroll
    for (int p = 0; p < 16; ++p) {
        int tb = tb0 + p;
        int tt = tb >> 5, bb = tb & 31;
        char* base = g_xpimg + (size_t)tt * 32768;
        #pragma unroll
        for (int cc = 0; cc < 2; ++cc) {
            int hh = cc ? h1 : h0;
            float v = ((cc ? acc1[p] : acc0[p]) + (cc ? b1 : b0)) *
                      mask_w[(size_t)bb * H + hh];
            __half hb = __float2half_rn(v);
            int seg = hh >> 3;
            unsigned byte = SWZ((unsigned)((bb >> 3) * 1024 + (seg >> 3) * 4096 +
                                           (bb & 7) * 128 + (seg & 7) * 16 + (hh & 7) * 2));
            *(__half*)(base + byte) = hb;
        }
    }
}

__global__ void init_hc(const float* __restrict__ h0, const float* __restrict__ c0)
{
    if (blockIdx.x == 0 && threadIdx.x == 0) g_cntA3 = 0;
    float* hp = &g_h[0][0][0];
    float* cp = &g_c[0][0][0];
    for (int i = blockIdx.x * blockDim.x + threadIdx.x; i < L * BATCH * H;
         i += gridDim.x * blockDim.x)
        { hp[i] = h0[i]; cp[i] = c0[i]; }
}

// ---- persistent kernel ----
// dyn SMEM: Ubuf 4x16K @0..64K ; hxbuf 4x8K @65536..98304 ; W resident 4x16K @131072..196608
// C-phase: inp (hi only, 32K) @0..32K (reuses Ubuf region, time-separated)
#define SMEM_DYN (196608 + 1024)

__global__ void __launch_bounds__(NTHR, 1)
rnn_kernel(const float* __restrict__ G,
           const float* __restrict__ mask_u,
           const float* __restrict__ mask_w,
           float* __restrict__ out)
{
    extern __shared__ char smc_raw[];
    __shared__ float redA[16];
    __shared__ float ghA;
    __shared__ float sm_g[16][33];
    __shared__ float red[4][16][33];

    const int c    = blockIdx.x;
    const int tid  = threadIdx.x;
    const int wid  = tid >> 5;
    const int lane = tid & 31;

    uint32_t sbr = smem_u32(smc_raw);
    uint32_t sb  = (sbr + 1023u) & ~1023u;

    // A: CTA = (layer, batch)
    const int al  = c & 3;
    const int abt = c >> 2;
    // B: warp = 4 J strips x 4 batch strips
    const int rs = wid >> 2;
    const int cs = wid & 3;
    // C: warp = (K split, batch strip); thread = (row r16, batch cb)
    const int ks = wid >> 2;
    const int ns = wid & 3;
    const int cb   = wid * 2 + (lane & 1);
    const int r16  = lane >> 1;
    const int q    = r16 >> 2;
    const int ms   = r16 & 3;
    const int mg   = c * 4 + ms;
    const int crow = q * 512 + mg;

    // hoisted per-thread constants
    const float Gv   = G[al * H + tid];
    const float muv  = mask_u[((size_t)(al * BATCH + abt)) * H + tid];
    float mwv[3];
    #pragma unroll
    for (int l = 0; l < 3; ++l)
        mwv[l] = mask_w[((size_t)((l + 1) * BATCH + cb)) * H + mg];

    float* out_h = out;
    float* out_c = out + L * BATCH * H;
    float* out_g = out + 2 * L * BATCH * H;

    // A work: gate + gated-masked hidden -> hx fp16 (hi only) image
    auto do_A = [&](int t_out) {
        float hm = g_h[al][abt][tid] * muv;
        float s  = hm * Gv;
        #pragma unroll
        for (int o = 16; o; o >>= 1) s += __shfl_xor_sync(~0u, s, o);
        if (lane == 0) redA[wid] = s;
        __syncthreads();
        if (tid == 0) {
            float ss = 0.f;
            #pragma unroll
            for (int r = 0; r < 16; ++r) ss += redA[r];
            float gh = sigm(ss);
            ghA = gh;
            out_g[(size_t)(al * BATCH + abt) * TT + t_out] = gh;
        }
        __syncthreads();
        float v = ghA * hm;
        __half hb = __float2half_rn(v);
        int kg = al * 512 + tid;
        int chunk = kg >> 7, kl = kg & 127, seg = kl >> 3;
        unsigned byte = SWZ((unsigned)((abt >> 3) * 1024 + (seg >> 3) * 4096 +
                                       (abt & 7) * 128 + (seg & 7) * 16 + (kl & 7) * 2));
        *(__half*)(g_hximg + (size_t)chunk * 8192 + byte) = hb;
        if (al == 3) {
            __syncthreads();
            if (tid == 0) {
                __threadfence();
                atomicAdd(&g_cntA3, 1u);
            }
        }
    };

    // load resident W (all 4 layers, 64KB) into SMEM @131072
    {
        const char* wsrc = g_Wimg;
        #pragma unroll
        for (int i = 0; i < 8; ++i) {
            int idx = i * 512 + tid;               // 0..4095 (layer = idx>>10)
            int l = idx >> 10, off = idx & 1023;
            cp16(sb + 131072 + l * 16384 + off * 16,
                 wsrc + ((size_t)(l * 128 + c)) * 16384 + off * 16);
        }
        CP_COMMIT();
    }

    // peel: A for t=0, drain W load, then one grid sync before B(0)
    do_A(0);
    CP_WAIT(0);
    grid_sync();

    for (int t = 0; t < TT; ++t) {
        // layer-3 A for step t
        if (t >= 1 && al == 3) do_A(t);

        // ===== B: U-GEMM (fp16, hx hi-only), 4-buffer pipeline, 1 sync per chunk =====
        {
            float dh[4] = {0.f, 0.f, 0.f, 0.f};

            auto stageB = [&](int ck) {
                if (ck == 12) wait_cnt(&g_cntA3, 32u * (unsigned)(t + 1));
                int buf = ck & 3;
                const char* us = g_Uimg + (size_t)(c * 16 + ck) * 16384;
                #pragma unroll
                for (int i = 0; i < 2; ++i) {
                    int idx = i * 512 + tid;
                    cp16(sb + buf * 16384 + idx * 16, us + idx * 16);
                }
                const char* hs = g_hximg + (size_t)ck * 8192;
                cp16(sb + 65536 + buf * 8192 + tid * 16, hs + tid * 16);
            };

            stageB(0); CP_COMMIT();
            stageB(1); CP_COMMIT();
            for (int ck = 0; ck < 16; ++ck) {
                if (ck + 2 < 16) { stageB(ck + 2); CP_COMMIT(); }
                if (ck <= 13)      { CP_WAIT(2); }
                else if (ck == 14) { CP_WAIT(1); }
                else               { CP_WAIT(0); }
                __syncthreads();

                uint32_t au  = sb + (ck & 3) * 16384;
                uint32_t buh = sb + 65536 + (ck & 3) * 8192;
                #pragma unroll
                for (int g = 0; g < 4; ++g) {
                    uint32_t baddr = (g >> 1) * 4096 + (cs * 8 + (lane & 7)) * 128 +
                                     (g & 1) * 64 + (lane >> 3) * 16;
                    uint32_t bh[4];
                    ldsm_x4(bh, buh + SWZ(baddr));
                    #pragma unroll
                    for (int sh = 0; sh < 2; ++sh) {
                        int s = g * 2 + sh;
                        uint32_t aaddr = (s >> 2) * 8192 + (rs * 16 + (lane & 15)) * 128 +
                                         (s & 3) * 32 + (lane >> 4) * 16;
                        uint32_t ah[4];
                        ldsm_x4(ah, au + SWZ(aaddr));
                        mma_f16(dh, ah, bh[2 * sh], bh[2 * sh + 1]);
                    }
                }
            }
            __syncthreads();
            int m = c * 64 + rs * 16 + (lane >> 2);
            int n = cs * 8 + (lane & 3) * 2;
            g_ugemm[n][m]         = dh[0];
            g_ugemm[n + 1][m]     = dh[1];
            g_ugemm[n][m + 8]     = dh[2];
            g_ugemm[n + 1][m + 8] = dh[3];
        }
        grid_sync();

        // ===== C: serial layer chain, W resident, inp fp16 hi-only (R13 verbatim) =====
        #pragma unroll
        for (int l = 0; l < 4; ++l) {
            const char* isrc = (l == 0) ? (g_xpimg + (size_t)t * 32768)
                                        : (g_hinimg + (size_t)(l - 1) * 32768);
            #pragma unroll
            for (int i = 0; i < 4; ++i) {
                int idx = i * 512 + tid;
                cp16(sb + idx * 16, isrc + idx * 16);
            }
            CP_COMMIT();

            // embedded A for layer l-1, step t+1 (overlapped with cp.async)
            if (l >= 1 && t != TT - 1 && al == l - 1) do_A(t + 1);

            CP_WAIT(0);
            __syncthreads();

            float ug = g_ugemm[cb][l * G4 + crow];

            float ddh[4] = {0.f, 0.f, 0.f, 0.f};
            uint32_t wres = sb + 131072 + l * 16384;
            uint32_t ih = sb;
            #pragma unroll
            for (int gg = 0; gg < 4; ++gg) {
                uint32_t baddr = (ks * 2 + (gg >> 1)) * 4096 + (ns * 8 + (lane & 7)) * 128 +
                                 (gg & 1) * 64 + (lane >> 3) * 16;
                uint32_t bh[4];
                ldsm_x4(bh, ih + SWZ(baddr));
                #pragma unroll
                for (int jh = 0; jh < 2; ++jh) {
                    int s = ks * 8 + gg * 2 + jh;
                    uint32_t aaddr = (s >> 2) * 2048 + (lane & 15) * 128 +
                                     (s & 3) * 32 + (lane >> 4) * 16;
                    uint32_t ah[4];
                    ldsm_x4(ah, wres + SWZ(aaddr));
                    mma_f16(ddh, ah, bh[2 * jh], bh[2 * jh + 1]);
                }
            }
            {
                int m0 = lane >> 2, n0 = ns * 8 + (lane & 3) * 2;
                red[ks][m0][n0]         = ddh[0];
                red[ks][m0][n0 + 1]     = ddh[1];
                red[ks][m0 + 8][n0]     = ddh[2];
                red[ks][m0 + 8][n0 + 1] = ddh[3];
            }
            __syncthreads();

            float a = red[0][r16][cb] + red[1][r16][cb] +
                      red[2][r16][cb] + red[3][r16][cb] + ug;
            float act = (q == 2) ? tanh_f(a) : sigm(a);
            sm_g[r16][cb] = act;
            __syncthreads();
            if (q == 0) {
                float gf  = sm_g[4 + ms][cb];
                float gg_ = sm_g[8 + ms][cb];
                float go  = sm_g[12 + ms][cb];
                float cold = g_c[l][cb][mg];
                float cn = gf * cold + act * gg_;
                float hy = go * tanh_f(cn);
                g_c[l][cb][mg] = cn;
                g_h[l][cb][mg] = hy;
                if (l < 3) {
                    float hv = hy * mwv[l];
                    __half hb = __float2half_rn(hv);
                    int seg = mg >> 3;
                    unsigned byte = SWZ((unsigned)((cb >> 3) * 1024 + (seg >> 3) * 4096 +
                                                   (cb & 7) * 128 + (seg & 7) * 16 + (mg & 7) * 2));
                    *(__half*)(g_hinimg + (size_t)l * 32768 + byte) = hb;
                }
            }
            grid_sync();
        }
    }

    const float* hp = &g_h[0][0][0];
    const float* cp = &g_c[0][0][0];
    for (int idx = c * NTHR + tid; idx < L * BATCH * H; idx += NCTA * NTHR) {
        out_h[idx] = hp[idx];
        out_c[idx] = cp[idx];
    }
}

// ---- launch ----
extern "C" void kernel_launch(void* const* d_in, const int* in_sizes, int n_in,
                              void* d_out, int out_size)
{
    const float* x      = (const float*)d_in[0];
    const float* lin_w  = (const float*)d_in[1];
    const float* lin_b  = (const float*)d_in[2];
    const float* W      = (const float*)d_in[3];
    const float* U      = (const float*)d_in[4];
    const float* G      = (const float*)d_in[5];
    const float* mask_u = (const float*)d_in[6];
    const float* mask_w = (const float*)d_in[7];
    const float* h0     = (const float*)d_in[8];
    const float* c0     = (const float*)d_in[9];
    float* out = (float*)d_out;
    (void)in_sizes; (void)n_in; (void)out_size;

    prep_all<<<2048 + 512, 256>>>(U, W);
    xp_kernel<<<(TT * BATCH) / 16, 256>>>(x, lin_w, lin_b, mask_w);
    init_hc<<<64, 256>>>(h0, c0);

    cudaFuncSetAttribute(rnn_kernel, cudaFuncAttributeMaxDynamicSharedMemorySize, SMEM_DYN);
    rnn_kernel<<<NCTA, NTHR, SMEM_DYN>>>(G, mask_u, mask_w, out);
}

// round 17
// speedup vs baseline: 1.1827x; 1.0298x over previous
#include <cuda_runtime.h>
#include <cuda_fp16.h>
#include <math.h>
#include <stdint.h>

#define L     4
#define H     512
#define BATCH 32
#define TT    1024
#define G4    2048
#define LH    2048
#define JTOT  8192
#define NCTA  128
#define NTHR  512

#define SWZ(o) ((unsigned)(o) ^ (((unsigned)(o) >> 3) & 0x70u))

// ---- PTX helpers (base-target features only) ----
__device__ __forceinline__ uint32_t smem_u32(const void* p) {
    uint32_t a;
    asm("{ .reg .u64 t; cvta.to.shared.u64 t, %1; cvt.u32.u64 %0, t; }" : "=r"(a) : "l"(p));
    return a;
}
__device__ __forceinline__ void cp16(uint32_t dst, const void* src) {
    asm volatile("cp.async.cg.shared.global [%0], [%1], 16;" :: "r"(dst), "l"(src) : "memory");
}
#define CP_COMMIT() asm volatile("cp.async.commit_group;" ::: "memory")
#define CP_WAIT(n)  asm volatile("cp.async.wait_group %0;" :: "n"(n) : "memory")

__device__ __forceinline__ void ldsm_x4(uint32_t* r, uint32_t addr) {
    asm volatile("ldmatrix.sync.aligned.m8n8.x4.shared.b16 {%0,%1,%2,%3}, [%4];"
        : "=r"(r[0]), "=r"(r[1]), "=r"(r[2]), "=r"(r[3]) : "r"(addr));
}
__device__ __forceinline__ void mma_f16(float* d, const uint32_t* a, uint32_t b0, uint32_t b1) {
    asm volatile("mma.sync.aligned.m16n8k16.row.col.f32.f16.f16.f32 "
        "{%0,%1,%2,%3}, {%4,%5,%6,%7}, {%8,%9}, {%0,%1,%2,%3};"
        : "+f"(d[0]), "+f"(d[1]), "+f"(d[2]), "+f"(d[3])
        : "r"(a[0]), "r"(a[1]), "r"(a[2]), "r"(a[3]), "r"(b0), "r"(b1));
}
__device__ __forceinline__ void wait_cnt(const unsigned* p, unsigned target) {
    unsigned v;
    do {
        asm volatile("ld.acquire.gpu.u32 %0, [%1];" : "=r"(v) : "l"(p) : "memory");
    } while (v < target);
}
__device__ __forceinline__ float sigm(float x) { return 1.f / (1.f + __expf(-x)); }
__device__ __forceinline__ float tanh_f(float x) { return 1.f - 2.f / (1.f + __expf(2.f * x)); }

// ---- static device scratch ----
__device__ __align__(16) char g_Uimg[(size_t)128 * 16 * 16384];      // [c][chunk] 16KB fp16
__device__ __align__(16) char g_Wimg[(size_t)4 * 128 * 16384];       // [l][c] 16KB fp16
__device__ __align__(16) char g_xpimg[(size_t)TT * 32768];           // [t] fp16 hi only
__device__ __align__(16) char g_hinimg[(size_t)3 * 32768];           // [l] fp16 hi only
__device__ __align__(16) char g_hximg[(size_t)16 * 8192];            // [chunk] fp16 hi only
__device__ float g_h[L][BATCH][H];
__device__ float g_c[L][BATCH][H];
__device__ float g_ugemm[BATCH][JTOT];
__device__ unsigned g_cntA3;
__device__ unsigned g_cnt = 0;
__device__ volatile unsigned g_gen = 0;

// ---- software grid barrier (R6/R13-proven single hot line; FROZEN) ----
__device__ __forceinline__ void grid_sync()
{
    __syncthreads();
    if (threadIdx.x == 0) {
        unsigned g = g_gen;
        __threadfence();
        if (atomicAdd(&g_cnt, 1u) == NCTA - 1u) {
            g_cnt = 0;
            __threadfence();
            g_gen = g + 1u;
        } else {
            while (g_gen == g) { }
        }
        __threadfence();
    }
    __syncthreads();
}

// ---- prep kernels (merged: U blocks 0..2047, W blocks 2048..2559) ----
__global__ void prep_all(const float* __restrict__ U, const float* __restrict__ W)
{
    if (blockIdx.x < 2048) {
        int blk = blockIdx.x;                 // c*16 + chunk
        int c = blk >> 4, chunk = blk & 15;
        char* dst = g_Uimg + (size_t)blk * 16384;
        for (int i = threadIdx.x; i < 1024; i += 256) {
            int r = i >> 4, s8 = i & 15;
            const float* src = U + ((size_t)(c * 64 + r)) * LH + chunk * 128 + s8 * 8;
            __half hv[8];
            #pragma unroll
            for (int j = 0; j < 8; ++j) hv[j] = __float2half_rn(src[j]);
            unsigned byte = SWZ((unsigned)((r >> 3) * 1024 + (s8 >> 3) * 8192 +
                                           (r & 7) * 128 + (s8 & 7) * 16));
            *(uint4*)(dst + byte) = *(uint4*)hv;
        }
    } else {
        int blk = blockIdx.x - 2048;          // l*128 + c
        int l = blk >> 7, c = blk & 127;
        char* dst = g_Wimg + (size_t)blk * 16384;
        for (int i = threadIdx.x; i < 1024; i += 256) {
            int r = i >> 6, s8 = i & 63;
            int q = r >> 2, ms = r & 3;
            int wrow = q * 512 + c * 4 + ms;
            const float* src = W + ((size_t)(l * G4 + wrow)) * H + s8 * 8;
            __half hv[8];
            #pragma unroll
            for (int j = 0; j < 8; ++j) hv[j] = __float2half_rn(src[j]);
            unsigned byte = SWZ((unsigned)((r >> 3) * 1024 + (s8 >> 3) * 2048 +
                                           (r & 7) * 128 + (s8 & 7) * 16));
            *(uint4*)(dst + byte) = *(uint4*)hv;
        }
    }
}

__global__ void xp_kernel(const float* __restrict__ x,
                          const float* __restrict__ lin_w,
                          const float* __restrict__ lin_b,
                          const float* __restrict__ mask_w)
{
    __shared__ float xs[16][128];
    int tb0 = blockIdx.x * 16;
    int tid = threadIdx.x;
    #pragma unroll
    for (int r = 0; r < 8; ++r) {
        int e = r * 256 + tid;
        xs[e >> 7][e & 127] = x[(size_t)(tb0 + (e >> 7)) * 128 + (e & 127)];
    }
    __syncthreads();
    int h0 = tid, h1 = tid + 256;
    const float* w0 = lin_w + (size_t)h0 * 128;
    const float* w1 = lin_w + (size_t)h1 * 128;
    float acc0[16], acc1[16];
    #pragma unroll
    for (int p = 0; p < 16; ++p) { acc0[p] = 0.f; acc1[p] = 0.f; }
    for (int i = 0; i < 128; i += 4) {
        float4 a = *(const float4*)(w0 + i);
        float4 b = *(const float4*)(w1 + i);
        #pragma unroll
        for (int p = 0; p < 16; ++p) {
            float4 xv = *(const float4*)&xs[p][i];
            acc0[p] += a.x * xv.x + a.y * xv.y + a.z * xv.z + a.w * xv.w;
            acc1[p] += b.x * xv.x + b.y * xv.y + b.z * xv.z + b.w * xv.w;
        }
    }
    float b0 = lin_b[h0], b1 = lin_b[h1];
    #pragma unroll
    for (int p = 0; p < 16; ++p) {
        int tb = tb0 + p;
        int tt = tb >> 5, bb = tb & 31;
        char* base = g_xpimg + (size_t)tt * 32768;
        #pragma unroll
        for (int cc = 0; cc < 2; ++cc) {
            int hh = cc ? h1 : h0;
            float v = ((cc ? acc1[p] : acc0[p]) + (cc ? b1 : b0)) *
                      mask_w[(size_t)bb * H + hh];
            __half hb = __float2half_rn(v);
            int seg = hh >> 3;
            unsigned byte = SWZ((unsigned)((bb >> 3) * 1024 + (seg >> 3) * 4096 +
                                           (bb & 7) * 128 + (seg & 7) * 16 + (hh & 7) * 2));
            *(__half*)(base + byte) = hb;
        }
    }
}

__global__ void init_hc(const float* __restrict__ h0, const float* __restrict__ c0)
{
    if (blockIdx.x == 0 && threadIdx.x == 0) g_cntA3 = 0;
    float* hp = &g_h[0][0][0];
    float* cp = &g_c[0][0][0];
    for (int i = blockIdx.x * blockDim.x + threadIdx.x; i < L * BATCH * H;
         i += gridDim.x * blockDim.x)
        { hp[i] = h0[i]; cp[i] = c0[i]; }
}

// ---- persistent kernel ----
// dyn SMEM: Ubuf 2x32K @0..64K ; hxbuf 2x16K @65536..98304 ;
//           inp 32K @98304..131072 ; W resident 4x16K @131072..196608
#define INP_OFF 98304
#define SMEM_DYN (196608 + 1024)

__global__ void __launch_bounds__(NTHR, 1)
rnn_kernel(const float* __restrict__ G,
           const float* __restrict__ mask_u,
           const float* __restrict__ mask_w,
           float* __restrict__ out)
{
    extern __shared__ char smc_raw[];
    __shared__ float redA[16];
    __shared__ float ghA;
    __shared__ float sm_g[16][33];
    __shared__ float red[4][16][33];

    const int c    = blockIdx.x;
    const int tid  = threadIdx.x;
    const int wid  = tid >> 5;
    const int lane = tid & 31;

    uint32_t sbr = smem_u32(smc_raw);
    uint32_t sb  = (sbr + 1023u) & ~1023u;

    // A: CTA = (layer, batch)
    const int al  = c & 3;
    const int abt = c >> 2;
    // B: warp = 4 J strips x 4 batch strips
    const int rs = wid >> 2;
    const int cs = wid & 3;
    // C: warp = (K split, batch strip); thread = (row r16, batch cb)
    const int ks = wid >> 2;
    const int ns = wid & 3;
    const int cb   = wid * 2 + (lane & 1);
    const int r16  = lane >> 1;
    const int q    = r16 >> 2;
    const int ms   = r16 & 3;
    const int mg   = c * 4 + ms;
    const int crow = q * 512 + mg;

    // hoisted per-thread constants
    const float Gv   = G[al * H + tid];
    const float muv  = mask_u[((size_t)(al * BATCH + abt)) * H + tid];
    float mwv[3];
    #pragma unroll
    for (int l = 0; l < 3; ++l)
        mwv[l] = mask_w[((size_t)((l + 1) * BATCH + cb)) * H + mg];

    float* out_h = out;
    float* out_c = out + L * BATCH * H;
    float* out_g = out + 2 * L * BATCH * H;

    // A work: gate + gated-masked hidden -> hx fp16 (hi only) image
    auto do_A = [&](int t_out) {
        float hm = g_h[al][abt][tid] * muv;
        float s  = hm * Gv;
        #pragma unroll
        for (int o = 16; o; o >>= 1) s += __shfl_xor_sync(~0u, s, o);
        if (lane == 0) redA[wid] = s;
        __syncthreads();
        if (tid == 0) {
            float ss = 0.f;
            #pragma unroll
            for (int r = 0; r < 16; ++r) ss += redA[r];
            float gh = sigm(ss);
            ghA = gh;
            out_g[(size_t)(al * BATCH + abt) * TT + t_out] = gh;
        }
        __syncthreads();
        float v = ghA * hm;
        __half hb = __float2half_rn(v);
        int kg = al * 512 + tid;
        int chunk = kg >> 7, kl = kg & 127, seg = kl >> 3;
        unsigned byte = SWZ((unsigned)((abt >> 3) * 1024 + (seg >> 3) * 4096 +
                                       (abt & 7) * 128 + (seg & 7) * 16 + (kl & 7) * 2));
        *(__half*)(g_hximg + (size_t)chunk * 8192 + byte) = hb;
        if (al == 3) {
            __syncthreads();
            if (tid == 0) {
                __threadfence();
                atomicAdd(&g_cntA3, 1u);
            }
        }
    };

    // load resident W (all 4 layers, 64KB) into SMEM @131072
    {
        const char* wsrc = g_Wimg;
        #pragma unroll
        for (int i = 0; i < 8; ++i) {
            int idx = i * 512 + tid;               // 0..4095 (layer = idx>>10)
            int l = idx >> 10, off = idx & 1023;
            cp16(sb + 131072 + l * 16384 + off * 16,
                 wsrc + ((size_t)(l * 128 + c)) * 16384 + off * 16);
        }
        CP_COMMIT();
    }

    // peel: A for t=0, drain W load, then one grid sync before B(0)
    do_A(0);
    CP_WAIT(0);
    grid_sync();

    for (int t = 0; t < TT; ++t) {
        // layer-3 A for step t
        if (t >= 1 && al == 3) do_A(t);

        // ===== B: U-GEMM (fp16, hx hi-only), 8 super-chunks of K=256 =====
        {
            float dh[4] = {0.f, 0.f, 0.f, 0.f};

            // stage super-chunk sck (two contiguous 128-K chunk images)
            auto stageB = [&](int sck) {
                if (sck == 6) wait_cnt(&g_cntA3, 32u * (unsigned)(t + 1));
                int buf = sck & 1;
                const char* us = g_Uimg + (size_t)(c * 16 + sck * 2) * 16384;  // 32KB
                #pragma unroll
                for (int i = 0; i < 4; ++i) {
                    int idx = i * 512 + tid;
                    cp16(sb + buf * 32768 + idx * 16, us + idx * 16);
                }
                const char* hs = g_hximg + (size_t)(sck * 2) * 8192;           // 16KB
                #pragma unroll
                for (int i = 0; i < 2; ++i) {
                    int idx = i * 512 + tid;
                    cp16(sb + 65536 + buf * 16384 + idx * 16, hs + idx * 16);
                }
            };

            // prologue: layer-0 inp for C (known at step start) + first super-chunk
            {
                const char* isrc = g_xpimg + (size_t)t * 32768;
                #pragma unroll
                for (int i = 0; i < 4; ++i) {
                    int idx = i * 512 + tid;
                    cp16(sb + INP_OFF + idx * 16, isrc + idx * 16);
                }
                stageB(0);
                CP_COMMIT();
            }

            for (int sck = 0; sck < 8; ++sck) {
                CP_WAIT(0);
                __syncthreads();            // all warps done with buffer sck^1's last use
                if (sck + 1 < 8) { stageB(sck + 1); CP_COMMIT(); }

                #pragma unroll
                for (int s2 = 0; s2 < 2; ++s2) {
                    uint32_t au  = sb + (sck & 1) * 32768 + s2 * 16384;
                    uint32_t buh = sb + 65536 + (sck & 1) * 16384 + s2 * 8192;
                    #pragma unroll
                    for (int g = 0; g < 4; ++g) {
                        uint32_t baddr = (g >> 1) * 4096 + (cs * 8 + (lane & 7)) * 128 +
                                         (g & 1) * 64 + (lane >> 3) * 16;
                        uint32_t bh[4];
                        ldsm_x4(bh, buh + SWZ(baddr));
                        #pragma unroll
                        for (int sh = 0; sh < 2; ++sh) {
                            int s = g * 2 + sh;
                            uint32_t aaddr = (s >> 2) * 8192 + (rs * 16 + (lane & 15)) * 128 +
                                             (s & 3) * 32 + (lane >> 4) * 16;
                            uint32_t ah[4];
                            ldsm_x4(ah, au + SWZ(aaddr));
                            mma_f16(dh, ah, bh[2 * sh], bh[2 * sh + 1]);
                        }
                    }
                }
            }
            __syncthreads();
            int m = c * 64 + rs * 16 + (lane >> 2);
            int n = cs * 8 + (lane & 3) * 2;
            g_ugemm[n][m]         = dh[0];
            g_ugemm[n + 1][m]     = dh[1];
            g_ugemm[n][m + 8]     = dh[2];
            g_ugemm[n + 1][m + 8] = dh[3];
        }
        grid_sync();

        // ===== C: serial layer chain, W resident, inp fp16 hi-only =====
        #pragma unroll
        for (int l = 0; l < 4; ++l) {
            if (l > 0) {
                const char* isrc = g_hinimg + (size_t)(l - 1) * 32768;
                #pragma unroll
                for (int i = 0; i < 4; ++i) {
                    int idx = i * 512 + tid;
                    cp16(sb + INP_OFF + idx * 16, isrc + idx * 16);
                }
                CP_COMMIT();

                // embedded A for layer l-1, step t+1 (overlapped with cp.async)
                if (t != TT - 1 && al == l - 1) do_A(t + 1);

                CP_WAIT(0);
                __syncthreads();
            }
            // l == 0: inp already staged during B and drained by B's CP_WAIT(0)

            float ug = g_ugemm[cb][l * G4 + crow];

            float ddh[4] = {0.f, 0.f, 0.f, 0.f};
            uint32_t wres = sb + 131072 + l * 16384;
            uint32_t ih = sb + INP_OFF;
            #pragma unroll
            for (int gg = 0; gg < 4; ++gg) {
                uint32_t baddr = (ks * 2 + (gg >> 1)) * 4096 + (ns * 8 + (lane & 7)) * 128 +
                                 (gg & 1) * 64 + (lane >> 3) * 16;
                uint32_t bh[4];
                ldsm_x4(bh, ih + SWZ(baddr));
                #pragma unroll
                for (int jh = 0; jh < 2; ++jh) {
                    int s = ks * 8 + gg * 2 + jh;
                    uint32_t aaddr = (s >> 2) * 2048 + (lane & 15) * 128 +
                                     (s & 3) * 32 + (lane >> 4) * 16;
                    uint32_t ah[4];
                    ldsm_x4(ah, wres + SWZ(aaddr));
                    mma_f16(ddh, ah, bh[2 * jh], bh[2 * jh + 1]);
                }
            }
            {
                int m0 = lane >> 2, n0 = ns * 8 + (lane & 3) * 2;
                red[ks][m0][n0]         = ddh[0];
                red[ks][m0][n0 + 1]     = ddh[1];
                red[ks][m0 + 8][n0]     = ddh[2];
                red[ks][m0 + 8][n0 + 1] = ddh[3];
            }
            __syncthreads();

            float a = red[0][r16][cb] + red[1][r16][cb] +
                      red[2][r16][cb] + red[3][r16][cb] + ug;
            float act = (q == 2) ? tanh_f(a) : sigm(a);
            sm_g[r16][cb] = act;
            __syncthreads();
            if (q == 0) {
                float gf  = sm_g[4 + ms][cb];
                float gg_ = sm_g[8 + ms][cb];
                float go  = sm_g[12 + ms][cb];
                float cold = g_c[l][cb][mg];
                float cn = gf * cold + act * gg_;
                float hy = go * tanh_f(cn);
                g_c[l][cb][mg] = cn;
                g_h[l][cb][mg] = hy;
                if (l < 3) {
                    float hv = hy * mwv[l];
                    __half hb = __float2half_rn(hv);
                    int seg = mg >> 3;
                    unsigned byte = SWZ((unsigned)((cb >> 3) * 1024 + (seg >> 3) * 4096 +
                                                   (cb & 7) * 128 + (seg & 7) * 16 + (mg & 7) * 2));
                    *(__half*)(g_hinimg + (size_t)l * 32768 + byte) = hb;
                }
            }
            grid_sync();
        }
    }

    const float* hp = &g_h[0][0][0];
    const float* cp = &g_c[0][0][0];
    for (int idx = c * NTHR + tid; idx < L * BATCH * H; idx += NCTA * NTHR) {
        out_h[idx] = hp[idx];
        out_c[idx] = cp[idx];
    }
}

// ---- launch ----
extern "C" void kernel_launch(void* const* d_in, const int* in_sizes, int n_in,
                              void* d_out, int out_size)
{
    const float* x      = (const float*)d_in[0];
    const float* lin_w  = (const float*)d_in[1];
    const float* lin_b  = (const float*)d_in[2];
    const float* W      = (const float*)d_in[3];
    const float* U      = (const float*)d_in[4];
    const float* G      = (const float*)d_in[5];
    const float* mask_u = (const float*)d_in[6];
    const float* mask_w = (const float*)d_in[7];
    const float* h0     = (const float*)d_in[8];
    const float* c0     = (const float*)d_in[9];
    float* out = (float*)d_out;
    (void)in_sizes; (void)n_in; (void)out_size;

    prep_all<<<2048 + 512, 256>>>(U, W);
    xp_kernel<<<(TT * BATCH) / 16, 256>>>(x, lin_w, lin_b, mask_w);
    init_hc<<<64, 256>>>(h0, c0);

    cudaFuncSetAttribute(rnn_kernel, cudaFuncAttributeMaxDynamicSharedMemorySize, SMEM_DYN);
    rnn_kernel<<<NCTA, NTHR, SMEM_DYN>>>(G, mask_u, mask_w, out);
}